// round 7
// baseline (speedup 1.0000x reference)
#include <cuda_runtime.h>
#include <cuda_bf16.h>
#include <cstdint>

#define NN 50000
#define NE 800000
#define D 256
#define DOUT 128
#define SCAN_B 49   // ceil(50000/1024)

// ---------------- device scratch (static: no allocation allowed) ----------------
__device__ float g_hf0[NN * D];            // fp32 h copies (for aggregation reads)
__device__ float g_hf1[NN * D];
__device__ unsigned short g_xH[NN * D],   g_xL[NN * D];    // bf16 hi/lo pairs
__device__ unsigned short g_h0H[NN * D],  g_h0L[NN * D];
__device__ unsigned short g_h1H[NN * D],  g_h1L[NN * D];
__device__ unsigned short g_aggH[NN * D], g_aggL[NN * D];  // also reused as z in post_mp
__device__ unsigned short g_wtH[8 * 65536], g_wtL[8 * 65536]; // transposed+split weights
__device__ float g_deginv[NN];
__device__ int   g_deg[NN];
__device__ int   g_rowptr[NN + 1];
__device__ int   g_cursor[NN];
__device__ int   g_col[NE];
__device__ int   g_bsum[SCAN_B];
__device__ int   g_is64;

// pair ids: 0 -> x, 1 -> h0, 2 -> h1, 3 -> agg/z
__device__ __forceinline__ unsigned short* pairH(int id) {
    if (id == 0) return g_xH;
    if (id == 1) return g_h0H;
    if (id == 2) return g_h1H;
    return g_aggH;
}
__device__ __forceinline__ unsigned short* pairL(int id) {
    if (id == 0) return g_xL;
    if (id == 1) return g_h0L;
    if (id == 2) return g_h1L;
    return g_aggL;
}

__device__ __forceinline__ int edge_at(const void* ei, int word) {
    if (g_is64) return (int)((const long long*)ei)[word];
    return ((const int*)ei)[word];
}

__device__ __forceinline__ uint32_t smem_u32(const void* p) {
    uint32_t a;
    asm("{ .reg .u64 t; cvta.to.shared.u64 t, %1; cvt.u32.u64 %0, t; }" : "=r"(a) : "l"(p));
    return a;
}
__device__ __forceinline__ void ldm4(uint32_t addr, uint32_t& r0, uint32_t& r1,
                                     uint32_t& r2, uint32_t& r3) {
    asm volatile("ldmatrix.sync.aligned.m8n8.x4.shared.b16 {%0,%1,%2,%3}, [%4];"
                 : "=r"(r0), "=r"(r1), "=r"(r2), "=r"(r3) : "r"(addr));
}
__device__ __forceinline__ void mma16816(float* c, const uint32_t* a, const uint32_t* b) {
    asm volatile("mma.sync.aligned.m16n8k16.row.col.f32.bf16.bf16.f32 "
                 "{%0,%1,%2,%3}, {%4,%5,%6,%7}, {%8,%9}, {%0,%1,%2,%3};"
                 : "+f"(c[0]), "+f"(c[1]), "+f"(c[2]), "+f"(c[3])
                 : "r"(a[0]), "r"(a[1]), "r"(a[2]), "r"(a[3]), "r"(b[0]), "r"(b[1]));
}
__device__ __forceinline__ void cpa16(uint32_t dst, const void* src, int valid) {
    asm volatile("cp.async.ca.shared.global [%0], [%1], 16, %2;"
                 :: "r"(dst), "l"(src), "r"(valid ? 16 : 0));
}
#define CP_COMMIT() asm volatile("cp.async.commit_group;" ::: "memory")
#define CP_WAIT2()  asm volatile("cp.async.wait_group 2;" ::: "memory")

// ---------------- splits ----------------
__global__ void k_split_x(const float* __restrict__ x) {
    int i = (blockIdx.x * blockDim.x + threadIdx.x) * 4;
    if (i >= NN * D) return;
#pragma unroll
    for (int j = 0; j < 4; j++) {
        float v = x[i + j];
        __nv_bfloat16 h = __float2bfloat16_rn(v);
        __nv_bfloat16 l = __float2bfloat16_rn(v - __bfloat162float(h));
        g_xH[i + j] = __bfloat16_as_ushort(h);
        g_xL[i + j] = __bfloat16_as_ushort(l);
    }
}

// transpose + split: WT[n][k] = W[k][n]; source W is [K, NC] row-major
__global__ void k_split_w(const float* __restrict__ W, int K, int NC, int off) {
    int t = blockIdx.x * blockDim.x + threadIdx.x;
    if (t >= K * NC) return;
    int k = t / NC, n = t % NC;
    float v = W[t];
    __nv_bfloat16 h = __float2bfloat16_rn(v);
    __nv_bfloat16 l = __float2bfloat16_rn(v - __bfloat162float(h));
    g_wtH[off + n * K + k] = __bfloat16_as_ushort(h);
    g_wtL[off + n * K + k] = __bfloat16_as_ushort(l);
}

// ---------------- dtype probe ----------------
__global__ void k_detect(const int* __restrict__ ei32) {
    __shared__ int nz;
    if (threadIdx.x == 0) nz = 0;
    __syncthreads();
    if (ei32[2 * threadIdx.x + 1] != 0) atomicOr(&nz, 1);
    __syncthreads();
    if (threadIdx.x == 0) g_is64 = nz ? 0 : 1;
}

// ---------------- CSR build ----------------
__global__ void k_zero_deg() {
    int i = blockIdx.x * blockDim.x + threadIdx.x;
    if (i < NN) g_deg[i] = 0;
}
__global__ void k_hist(const void* __restrict__ ei) {
    int e = blockIdx.x * blockDim.x + threadIdx.x;
    if (e < NE) {
        unsigned d = (unsigned)edge_at(ei, NE + e);
        if (d < NN) atomicAdd(&g_deg[d], 1);
    }
}
__global__ void k_scan1() {
    __shared__ int s[1024];
    int t = threadIdx.x;
    int i = blockIdx.x * 1024 + t;
    int v = (i < NN) ? g_deg[i] : 0;
    s[t] = v;
    __syncthreads();
    for (int o = 1; o < 1024; o <<= 1) {
        int a = (t >= o) ? s[t - o] : 0;
        __syncthreads();
        s[t] += a;
        __syncthreads();
    }
    if (i < NN) g_rowptr[i] = s[t] - v;
    if (t == 1023) g_bsum[blockIdx.x] = s[1023];
}
__global__ void k_scan2() {
    int run = 0;
    for (int b = 0; b < SCAN_B; b++) { int t = g_bsum[b]; g_bsum[b] = run; run += t; }
}
__global__ void k_scan3() {
    int i = blockIdx.x * blockDim.x + threadIdx.x;
    if (i < NN) {
        int rp = g_rowptr[i] + g_bsum[i >> 10];
        g_rowptr[i] = rp;
        g_cursor[i] = rp;
        int dg = g_deg[i];
        g_deginv[i] = 1.0f / (float)(dg > 0 ? dg : 1);
    }
    if (i == 0) g_rowptr[NN] = NE;
}
__global__ void k_fill(const void* __restrict__ ei) {
    int e = blockIdx.x * blockDim.x + threadIdx.x;
    if (e < NE) {
        unsigned d = (unsigned)edge_at(ei, NE + e);
        unsigned s = (unsigned)edge_at(ei, e);
        if (d < NN && s < NN) {
            int pos = atomicAdd(&g_cursor[d], 1);
            g_col[pos] = (int)s;
        }
    }
}

// ---------------- mean aggregation -> bf16 pair output ----------------
// src_id: 0 -> g_hf0, 1 -> g_hf1, 3 -> external x
__global__ void k_agg(const float* __restrict__ xext, int src_id) {
    const float* __restrict__ hin = (src_id == 0) ? g_hf0 : (src_id == 1) ? g_hf1 : xext;
    __shared__ int sc[256];
    int t = threadIdx.x;
    for (int r = blockIdx.x; r < NN; r += gridDim.x) {
        int beg = g_rowptr[r], end = g_rowptr[r + 1];
        float acc = 0.f;
        for (int base = beg; base < end; base += 256) {
            int cnt = min(256, end - base);
            __syncthreads();
            if (t < cnt) sc[t] = g_col[base + t];
            __syncthreads();
            int i = 0;
            for (; i + 4 <= cnt; i += 4) {
                float a0 = hin[(size_t)sc[i]     * D + t];
                float a1 = hin[(size_t)sc[i + 1] * D + t];
                float a2 = hin[(size_t)sc[i + 2] * D + t];
                float a3 = hin[(size_t)sc[i + 3] * D + t];
                acc += (a0 + a1) + (a2 + a3);
            }
            for (; i < cnt; i++) acc += hin[(size_t)sc[i] * D + t];
        }
        float v = acc * g_deginv[r];
        __nv_bfloat16 h = __float2bfloat16_rn(v);
        __nv_bfloat16 l = __float2bfloat16_rn(v - __bfloat162float(h));
        g_aggH[(size_t)r * D + t] = __bfloat16_as_ushort(h);
        g_aggL[(size_t)r * D + t] = __bfloat16_as_ushort(l);
    }
}

// ---------------- bf16-split tensor-core GEMM, 4-stage cp.async pipeline ----------------
// C[128x128 tile] = sum_src (AH+AL)@(WH+WL)^T  (3 products), fused bias(+relu).
// K-chunk 16; tiles AH/AL/BH/BL 128 rows x 16 bf16, 48 B padded rows (conflict-free).
#define TROWB   48
#define TILE_B  (128 * TROWB)       // 6144
#define STAGE_B (4 * TILE_B)        // 24576
#define NSTAGE  4
#define SMEM_DYN (NSTAGE * STAGE_B) // 98304 (96 KB)

__global__ __launch_bounds__(256, 2)
void k_mma(int a1id, int a2id, int dual, int outp, int f32sel,
           float* __restrict__ cext, int woff1, int woff2,
           const float* __restrict__ bias, int relu, int ldc) {
    extern __shared__ __align__(16) unsigned char sT[];
    uint32_t sb = smem_u32(sT);
    int tid = threadIdx.x;
    int lane = tid & 31;
    int wid = tid >> 5;
    int wm = wid & 1;        // 2 warp-rows (64 rows)
    int wn = wid >> 1;       // 4 warp-cols (32 cols)
    int bm = blockIdx.x * 128;
    int bn = blockIdx.y * 128;

    const unsigned short* pAH[2] = { pairH(a1id), pairH(a2id) };
    const unsigned short* pAL[2] = { pairL(a1id), pairL(a2id) };
    const unsigned short* pBH[2] = { g_wtH + woff1, g_wtH + woff2 };
    const unsigned short* pBL[2] = { g_wtL + woff1, g_wtL + woff2 };

    float acc[16][4];
#pragma unroll
    for (int i = 0; i < 16; i++)
#pragma unroll
        for (int j = 0; j < 4; j++) acc[i][j] = 0.f;

    // loader mapping: each thread fills one 16B segment per tile per stage
    int lrow = tid >> 1, seg = tid & 1;
    int gr = bm + lrow;
    int av = gr < NN;
    size_t aoff = (size_t)(av ? gr : 0) * D + seg * 8;
    size_t boff = (size_t)(bn + lrow) * D + seg * 8;
    uint32_t dbase = sb + (uint32_t)(lrow * TROWB + seg * 16);

    // ldmatrix lane-address components (proven mapping, stride 48)
    int grp = lane >> 3, lr = lane & 7;
    int a_r = wm * 64 + ((grp & 1) << 3) + lr;
    int a_c = (grp & 2) ? 8 : 0;
    int b_r = wn * 32 + ((grp & 2) << 2) + lr;
    int b_c = (grp & 1) << 3;
    uint32_t offA = (uint32_t)(a_r * TROWB + a_c * 2);
    uint32_t offB = (uint32_t)(b_r * TROWB + b_c * 2);

    int NIT = dual ? 32 : 16;

    // prologue: load iterations 0..2 into stages 0..2 (3 committed groups)
#pragma unroll
    for (int j = 0; j < 3; j++) {
        int s = j >> 4, kc = j & 15;
        uint32_t dst = dbase + (uint32_t)(j * STAGE_B);
        if (j < 16 || dual) {
            cpa16(dst,              pAH[s] + aoff + kc * 16, av);
            cpa16(dst + TILE_B,     pAL[s] + aoff + kc * 16, av);
            cpa16(dst + 2 * TILE_B, pBH[s] + boff + kc * 16, 1);
            cpa16(dst + 3 * TILE_B, pBL[s] + boff + kc * 16, 1);
        }
        CP_COMMIT();
    }

    for (int it = 0; it < NIT; it++) {
        CP_WAIT2();          // stage it%4 ready (leaves it+1, it+2 in flight)
        __syncthreads();     // data visible to all warps; compute it-1 fully drained

        // prefetch iteration it+3 into stage (it+3)%4 (that buffer was last used
        // by compute it-1, ordered by the barrier above)
        {
            int j = it + 3;
            uint32_t dst = dbase + (uint32_t)((j & 3) * STAGE_B);
            if (j < NIT) {
                int s = j >> 4, kc = j & 15;
                cpa16(dst,              pAH[s] + aoff + kc * 16, av);
                cpa16(dst + TILE_B,     pAL[s] + aoff + kc * 16, av);
                cpa16(dst + 2 * TILE_B, pBH[s] + boff + kc * 16, 1);
                cpa16(dst + 3 * TILE_B, pBL[s] + boff + kc * 16, 1);
            }
            CP_COMMIT();
        }

        uint32_t base = sb + (uint32_t)((it & 3) * STAGE_B);
        uint32_t bH[4][2], bL[4][2];
#pragma unroll
        for (int nb = 0; nb < 2; nb++) {
            uint32_t off = offB + (uint32_t)(nb * 16 * TROWB);
            uint32_t t0, t1, t2, t3;
            ldm4(base + 2 * TILE_B + off, t0, t1, t2, t3);
            bH[nb * 2][0] = t0; bH[nb * 2][1] = t1;
            bH[nb * 2 + 1][0] = t2; bH[nb * 2 + 1][1] = t3;
            ldm4(base + 3 * TILE_B + off, t0, t1, t2, t3);
            bL[nb * 2][0] = t0; bL[nb * 2][1] = t1;
            bL[nb * 2 + 1][0] = t2; bL[nb * 2 + 1][1] = t3;
        }
        uint32_t a[4];
#pragma unroll
        for (int mi = 0; mi < 4; mi++) {
            uint32_t off = offA + (uint32_t)(mi * 16 * TROWB);
            ldm4(base + off, a[0], a[1], a[2], a[3]);
#pragma unroll
            for (int nj = 0; nj < 4; nj++) {
                mma16816(acc[mi * 4 + nj], a, bH[nj]);
                mma16816(acc[mi * 4 + nj], a, bL[nj]);
            }
            ldm4(base + TILE_B + off, a[0], a[1], a[2], a[3]);
#pragma unroll
            for (int nj = 0; nj < 4; nj++)
                mma16816(acc[mi * 4 + nj], a, bH[nj]);
        }
    }

    // epilogue (proven)
    unsigned short* oH = (outp >= 0) ? pairH(outp) : nullptr;
    unsigned short* oL = (outp >= 0) ? pairL(outp) : nullptr;
    float* f32d = (f32sel == 0) ? g_hf0 : (f32sel == 1) ? g_hf1 : cext;
#pragma unroll
    for (int mi = 0; mi < 4; mi++) {
#pragma unroll
        for (int nj = 0; nj < 4; nj++) {
            float* c = acc[mi * 4 + nj];
            int col = bn + wn * 32 + nj * 8 + (lane & 3) * 2;
            float bi0 = bias[col], bi1 = bias[col + 1];
#pragma unroll
            for (int half = 0; half < 2; half++) {
                int r = bm + wm * 64 + mi * 16 + (lane >> 2) + half * 8;
                if (r >= NN) continue;
                float v0 = c[half * 2] + bi0;
                float v1 = c[half * 2 + 1] + bi1;
                if (relu) { v0 = fmaxf(v0, 0.f); v1 = fmaxf(v1, 0.f); }
                if (oH) {
                    __nv_bfloat16 h0 = __float2bfloat16_rn(v0);
                    __nv_bfloat16 h1 = __float2bfloat16_rn(v1);
                    unsigned short l0 = __bfloat16_as_ushort(
                        __float2bfloat16_rn(v0 - __bfloat162float(h0)));
                    unsigned short l1 = __bfloat16_as_ushort(
                        __float2bfloat16_rn(v1 - __bfloat162float(h1)));
                    size_t base = (size_t)r * D + col;
                    *(ushort2*)(oH + base) =
                        make_ushort2(__bfloat16_as_ushort(h0), __bfloat16_as_ushort(h1));
                    *(ushort2*)(oL + base) = make_ushort2(l0, l1);
                }
                if (f32sel >= 0)
                    *(float2*)(f32d + (size_t)r * ldc + col) = make_float2(v0, v1);
            }
        }
    }
}

// ---------------- row-wise log_softmax over 128 cols, in place ----------------
__global__ void k_lsm(float* __restrict__ out) {
    int r = blockIdx.x;
    int t = threadIdx.x;
    float v = out[(size_t)r * DOUT + t];
    __shared__ float smax[4], ssum[4];
    float m = v;
#pragma unroll
    for (int o = 16; o; o >>= 1) m = fmaxf(m, __shfl_xor_sync(0xffffffffu, m, o));
    if ((t & 31) == 0) smax[t >> 5] = m;
    __syncthreads();
    float mm = fmaxf(fmaxf(smax[0], smax[1]), fmaxf(smax[2], smax[3]));
    float e = expf(v - mm);
    float sum = e;
#pragma unroll
    for (int o = 16; o; o >>= 1) sum += __shfl_xor_sync(0xffffffffu, sum, o);
    if ((t & 31) == 0) ssum[t >> 5] = sum;
    __syncthreads();
    float tot = ssum[0] + ssum[1] + ssum[2] + ssum[3];
    out[(size_t)r * DOUT + t] = v - mm - logf(tot);
}

// ---------------- launch: kernel launches ONLY ----------------
extern "C" void kernel_launch(void* const* d_in, const int* in_sizes, int n_in,
                              void* d_out, int out_size) {
    const float* x  = (const float*)d_in[0];
    const void*  ei = d_in[1];
    const float* wl = (const float*)d_in[2];
    const float* bl = (const float*)d_in[3];
    const float* wr = (const float*)d_in[4];
    const float* w1 = (const float*)d_in[5];
    const float* b1 = (const float*)d_in[6];
    const float* w2 = (const float*)d_in[7];
    const float* b2 = (const float*)d_in[8];
    float* out = (float*)d_out;

    // enable 96 KB dynamic smem for k_mma (idempotent; not a stream op)
    cudaFuncSetAttribute(k_mma, cudaFuncAttributeMaxDynamicSharedMemorySize, SMEM_DYN);

    // operand prep
    k_split_x<<<(NN * D / 4 + 255) / 256, 256>>>(x);
    for (int l = 0; l < 3; l++) {
        k_split_w<<<(D * D + 255) / 256, 256>>>(wl + (size_t)l * D * D, D, D, l * 65536);
        k_split_w<<<(D * D + 255) / 256, 256>>>(wr + (size_t)l * D * D, D, D, (3 + l) * 65536);
    }
    k_split_w<<<(D * D + 255) / 256, 256>>>(w1, D, D, 6 * 65536);
    k_split_w<<<(D * DOUT + 255) / 256, 256>>>(w2, D, DOUT, 7 * 65536);

    // CSR by dst
    k_detect<<<1, 512>>>((const int*)ei);
    k_zero_deg<<<(NN + 255) / 256, 256>>>();
    k_hist<<<(NE + 255) / 256, 256>>>(ei);
    k_scan1<<<SCAN_B, 1024>>>();
    k_scan2<<<1, 1>>>();
    k_scan3<<<(NN + 255) / 256, 256>>>();
    k_fill<<<(NE + 255) / 256, 256>>>(ei);

    dim3 g2((NN + 127) / 128, 2);
    dim3 g1((NN + 127) / 128, 1);

    // layer 0: agg(x); h0 = relu(agg@wl0 + x@wr0 + bl0)   (pair + fp32 copy -> g_hf0)
    k_agg<<<4096, 256>>>(x, 3);
    k_mma<<<g2, 256, SMEM_DYN>>>(3, 0, 1, 1, 0, nullptr, 0 * 65536, 3 * 65536, bl + 0 * D, 1, D);
    // layer 1: agg(h0); h1 = relu(...)                    (pair + fp32 copy -> g_hf1)
    k_agg<<<4096, 256>>>(nullptr, 0);
    k_mma<<<g2, 256, SMEM_DYN>>>(3, 1, 1, 2, 1, nullptr, 1 * 65536, 4 * 65536, bl + 1 * D, 1, D);
    // layer 2: agg(h1); h0 = relu(...)                    (pair only)
    k_agg<<<4096, 256>>>(nullptr, 1);
    k_mma<<<g2, 256, SMEM_DYN>>>(3, 2, 1, 1, -1, nullptr, 2 * 65536, 5 * 65536, bl + 2 * D, 1, D);
    // post_mp: z = h0@w1 + b1 (pair -> agg bufs); out = z@w2 + b2 (fp32 ext)
    k_mma<<<g2, 256, SMEM_DYN>>>(1, 1, 0, 3, -1, nullptr, 6 * 65536, 0, b1, 0, D);
    k_mma<<<g1, 256, SMEM_DYN>>>(3, 3, 0, -1, 2, out, 7 * 65536, 0, b2, 0, DOUT);
    k_lsm<<<NN, 128>>>(out);
}

// round 8
// speedup vs baseline: 1.0705x; 1.0705x over previous
#include <cuda_runtime.h>
#include <cuda_bf16.h>
#include <cstdint>

#define NN 50000
#define NE 800000
#define D 256
#define DOUT 128
#define SCAN_B 49   // ceil(50000/1024)

// ---------------- device scratch (static: no allocation allowed) ----------------
__device__ float g_hf0[NN * D];            // fp32 h copies (for aggregation reads)
__device__ float g_hf1[NN * D];
__device__ unsigned short g_xH[NN * D],   g_xL[NN * D];    // bf16 hi/lo pairs
__device__ unsigned short g_h0H[NN * D],  g_h0L[NN * D];
__device__ unsigned short g_h1H[NN * D],  g_h1L[NN * D];
__device__ unsigned short g_aggH[NN * D], g_aggL[NN * D];  // also reused as z in post_mp
__device__ unsigned short g_wtH[8 * 65536], g_wtL[8 * 65536]; // transposed+split weights
__device__ float g_deginv[NN];
__device__ int   g_deg[NN];
__device__ int   g_rowptr[NN + 1];
__device__ int   g_cursor[NN];
__device__ int   g_col[NE];
__device__ int   g_bsum[SCAN_B];
__device__ int   g_is64;

// pair ids: 0 -> x, 1 -> h0, 2 -> h1, 3 -> agg/z
__device__ __forceinline__ unsigned short* pairH(int id) {
    if (id == 0) return g_xH;
    if (id == 1) return g_h0H;
    if (id == 2) return g_h1H;
    return g_aggH;
}
__device__ __forceinline__ unsigned short* pairL(int id) {
    if (id == 0) return g_xL;
    if (id == 1) return g_h0L;
    if (id == 2) return g_h1L;
    return g_aggL;
}

__device__ __forceinline__ int edge_at(const void* ei, int word) {
    if (g_is64) return (int)((const long long*)ei)[word];
    return ((const int*)ei)[word];
}

__device__ __forceinline__ uint32_t smem_u32(const void* p) {
    uint32_t a;
    asm("{ .reg .u64 t; cvta.to.shared.u64 t, %1; cvt.u32.u64 %0, t; }" : "=r"(a) : "l"(p));
    return a;
}
__device__ __forceinline__ void ldm4(uint32_t addr, uint32_t& r0, uint32_t& r1,
                                     uint32_t& r2, uint32_t& r3) {
    asm volatile("ldmatrix.sync.aligned.m8n8.x4.shared.b16 {%0,%1,%2,%3}, [%4];"
                 : "=r"(r0), "=r"(r1), "=r"(r2), "=r"(r3) : "r"(addr));
}
__device__ __forceinline__ void mma16816(float* c, const uint32_t* a, const uint32_t* b) {
    asm volatile("mma.sync.aligned.m16n8k16.row.col.f32.bf16.bf16.f32 "
                 "{%0,%1,%2,%3}, {%4,%5,%6,%7}, {%8,%9}, {%0,%1,%2,%3};"
                 : "+f"(c[0]), "+f"(c[1]), "+f"(c[2]), "+f"(c[3])
                 : "r"(a[0]), "r"(a[1]), "r"(a[2]), "r"(a[3]), "r"(b[0]), "r"(b[1]));
}
__device__ __forceinline__ void cpa16(uint32_t dst, const void* src, int valid) {
    asm volatile("cp.async.cg.shared.global [%0], [%1], 16, %2;"
                 :: "r"(dst), "l"(src), "r"(valid ? 16 : 0));
}
#define CP_COMMIT() asm volatile("cp.async.commit_group;" ::: "memory")
#define CP_WAIT1()  asm volatile("cp.async.wait_group 1;" ::: "memory")
#define CP_WAIT0()  asm volatile("cp.async.wait_group 0;" ::: "memory")

// ---------------- splits ----------------
__global__ void k_split_x(const float* __restrict__ x) {
    int i = (blockIdx.x * blockDim.x + threadIdx.x) * 4;
    if (i >= NN * D) return;
#pragma unroll
    for (int j = 0; j < 4; j++) {
        float v = x[i + j];
        __nv_bfloat16 h = __float2bfloat16_rn(v);
        __nv_bfloat16 l = __float2bfloat16_rn(v - __bfloat162float(h));
        g_xH[i + j] = __bfloat16_as_ushort(h);
        g_xL[i + j] = __bfloat16_as_ushort(l);
    }
}

// transpose + split: WT[n][k] = W[k][n]; source W is [K, NC] row-major
__global__ void k_split_w(const float* __restrict__ W, int K, int NC, int off) {
    int t = blockIdx.x * blockDim.x + threadIdx.x;
    if (t >= K * NC) return;
    int k = t / NC, n = t % NC;
    float v = W[t];
    __nv_bfloat16 h = __float2bfloat16_rn(v);
    __nv_bfloat16 l = __float2bfloat16_rn(v - __bfloat162float(h));
    g_wtH[off + n * K + k] = __bfloat16_as_ushort(h);
    g_wtL[off + n * K + k] = __bfloat16_as_ushort(l);
}

// ---------------- dtype probe ----------------
__global__ void k_detect(const int* __restrict__ ei32) {
    __shared__ int nz;
    if (threadIdx.x == 0) nz = 0;
    __syncthreads();
    if (ei32[2 * threadIdx.x + 1] != 0) atomicOr(&nz, 1);
    __syncthreads();
    if (threadIdx.x == 0) g_is64 = nz ? 0 : 1;
}

// ---------------- CSR build ----------------
__global__ void k_zero_deg() {
    int i = blockIdx.x * blockDim.x + threadIdx.x;
    if (i < NN) g_deg[i] = 0;
}
__global__ void k_hist(const void* __restrict__ ei) {
    int e = blockIdx.x * blockDim.x + threadIdx.x;
    if (e < NE) {
        unsigned d = (unsigned)edge_at(ei, NE + e);
        if (d < NN) atomicAdd(&g_deg[d], 1);
    }
}
__global__ void k_scan1() {
    __shared__ int s[1024];
    int t = threadIdx.x;
    int i = blockIdx.x * 1024 + t;
    int v = (i < NN) ? g_deg[i] : 0;
    s[t] = v;
    __syncthreads();
    for (int o = 1; o < 1024; o <<= 1) {
        int a = (t >= o) ? s[t - o] : 0;
        __syncthreads();
        s[t] += a;
        __syncthreads();
    }
    if (i < NN) g_rowptr[i] = s[t] - v;
    if (t == 1023) g_bsum[blockIdx.x] = s[1023];
}
__global__ void k_scan2() {
    int run = 0;
    for (int b = 0; b < SCAN_B; b++) { int t = g_bsum[b]; g_bsum[b] = run; run += t; }
}
__global__ void k_scan3() {
    int i = blockIdx.x * blockDim.x + threadIdx.x;
    if (i < NN) {
        int rp = g_rowptr[i] + g_bsum[i >> 10];
        g_rowptr[i] = rp;
        g_cursor[i] = rp;
        int dg = g_deg[i];
        g_deginv[i] = 1.0f / (float)(dg > 0 ? dg : 1);
    }
    if (i == 0) g_rowptr[NN] = NE;
}
__global__ void k_fill(const void* __restrict__ ei) {
    int e = blockIdx.x * blockDim.x + threadIdx.x;
    if (e < NE) {
        unsigned d = (unsigned)edge_at(ei, NE + e);
        unsigned s = (unsigned)edge_at(ei, e);
        if (d < NN && s < NN) {
            int pos = atomicAdd(&g_cursor[d], 1);
            g_col[pos] = (int)s;
        }
    }
}

// ---------------- mean aggregation -> bf16 pair output ----------------
// src_id: 0 -> g_hf0, 1 -> g_hf1, 3 -> external x
__global__ void k_agg(const float* __restrict__ xext, int src_id) {
    const float* __restrict__ hin = (src_id == 0) ? g_hf0 : (src_id == 1) ? g_hf1 : xext;
    __shared__ int sc[256];
    int t = threadIdx.x;
    for (int r = blockIdx.x; r < NN; r += gridDim.x) {
        int beg = g_rowptr[r], end = g_rowptr[r + 1];
        float acc = 0.f;
        for (int base = beg; base < end; base += 256) {
            int cnt = min(256, end - base);
            __syncthreads();
            if (t < cnt) sc[t] = g_col[base + t];
            __syncthreads();
            int i = 0;
            for (; i + 4 <= cnt; i += 4) {
                float a0 = hin[(size_t)sc[i]     * D + t];
                float a1 = hin[(size_t)sc[i + 1] * D + t];
                float a2 = hin[(size_t)sc[i + 2] * D + t];
                float a3 = hin[(size_t)sc[i + 3] * D + t];
                acc += (a0 + a1) + (a2 + a3);
            }
            for (; i < cnt; i++) acc += hin[(size_t)sc[i] * D + t];
        }
        float v = acc * g_deginv[r];
        __nv_bfloat16 h = __float2bfloat16_rn(v);
        __nv_bfloat16 l = __float2bfloat16_rn(v - __bfloat162float(h));
        g_aggH[(size_t)r * D + t] = __bfloat16_as_ushort(h);
        g_aggL[(size_t)r * D + t] = __bfloat16_as_ushort(l);
    }
}

// ---------------- bf16-split tensor-core GEMM, 2-stage cp.async, K-chunk 32 ----------------
// C[128x128 tile] = sum_src (AH+AL)@(WH+WL)^T  (3 products), fused bias(+relu).
// Tiles AH/AL/BH/BL 128 rows x 32 bf16, 80 B padded rows (conflict-free ldmatrix).
#define TROWB   80
#define TILE_B  (128 * TROWB)       // 10240
#define STAGE_B (4 * TILE_B)        // 40960
#define SMEM_DYN (2 * STAGE_B)      // 81920 (80 KB)

__global__ __launch_bounds__(256, 2)
void k_mma(int a1id, int a2id, int dual, int outp, int f32sel,
           float* __restrict__ cext, int woff1, int woff2,
           const float* __restrict__ bias, int relu, int ldc) {
    extern __shared__ __align__(16) unsigned char sT[];
    uint32_t sb = smem_u32(sT);
    int tid = threadIdx.x;
    int lane = tid & 31;
    int wid = tid >> 5;
    int wm = wid & 1;        // 2 warp-rows (64 rows)
    int wn = wid >> 1;       // 4 warp-cols (32 cols)
    int bm = blockIdx.x * 128;
    int bn = blockIdx.y * 128;

    const unsigned short* pAH[2] = { pairH(a1id), pairH(a2id) };
    const unsigned short* pAL[2] = { pairL(a1id), pairL(a2id) };
    const unsigned short* pBH[2] = { g_wtH + woff1, g_wtH + woff2 };
    const unsigned short* pBL[2] = { g_wtL + woff1, g_wtL + woff2 };

    float acc[16][4];
#pragma unroll
    for (int i = 0; i < 16; i++)
#pragma unroll
        for (int j = 0; j < 4; j++) acc[i][j] = 0.f;

    // loader mapping: 128 rows x 32 bf16 (64 B) per tile; thread -> (row, 16B seg pair)
    int lrow = tid >> 1, s0 = tid & 1;
    int gr = bm + lrow;
    int av = gr < NN;
    size_t arow = (size_t)(av ? gr : 0) * D;
    size_t brow = (size_t)(bn + lrow) * D;
    uint32_t drow = sb + (uint32_t)(lrow * TROWB);

    // ldmatrix lane-address components (round-5 proven mapping, stride 80)
    int grp = lane >> 3, lr = lane & 7;
    int a_r = wm * 64 + ((grp & 1) << 3) + lr;
    int a_c = (grp & 2) ? 8 : 0;
    int b_r = wn * 32 + ((grp & 2) << 2) + lr;
    int b_c = (grp & 1) << 3;
    uint32_t offA = (uint32_t)(a_r * TROWB + a_c * 2);
    uint32_t offB = (uint32_t)(b_r * TROWB + b_c * 2);

    int NIT = dual ? 16 : 8;

    // prologue: iteration 0 -> stage 0
#pragma unroll
    for (int j2 = 0; j2 < 2; j2++) {
        int seg = s0 + 2 * j2;                 // 16B segment 0..3 within 64B row
        uint32_t d = drow + (uint32_t)(seg * 16);
        size_t go = (size_t)(seg * 8);
        cpa16(d,              pAH[0] + arow + go, av);
        cpa16(d + TILE_B,     pAL[0] + arow + go, av);
        cpa16(d + 2 * TILE_B, pBH[0] + brow + go, 1);
        cpa16(d + 3 * TILE_B, pBL[0] + brow + go, 1);
    }
    CP_COMMIT();

    for (int it = 0; it < NIT; it++) {
        // prefetch it+1 into the other stage (its prior use drained by loop-end sync)
        if (it + 1 < NIT) {
            int s = (it + 1) >> 3, kc = (it + 1) & 7;
            uint32_t stg = (uint32_t)(((it + 1) & 1) * STAGE_B);
#pragma unroll
            for (int j2 = 0; j2 < 2; j2++) {
                int seg = s0 + 2 * j2;
                uint32_t d = drow + stg + (uint32_t)(seg * 16);
                size_t go = (size_t)(kc * 32 + seg * 8);
                cpa16(d,              pAH[s] + arow + go, av);
                cpa16(d + TILE_B,     pAL[s] + arow + go, av);
                cpa16(d + 2 * TILE_B, pBH[s] + brow + go, 1);
                cpa16(d + 3 * TILE_B, pBL[s] + brow + go, 1);
            }
            CP_COMMIT();
            CP_WAIT1();
        } else {
            CP_WAIT0();
        }
        __syncthreads();

        uint32_t base = sb + (uint32_t)((it & 1) * STAGE_B);
#pragma unroll
        for (int kk = 0; kk < 32; kk += 16) {
            uint32_t koff = (uint32_t)(kk * 2);
            uint32_t bH[4][2], bL[4][2];
#pragma unroll
            for (int nb = 0; nb < 2; nb++) {
                uint32_t off = offB + koff + (uint32_t)(nb * 16 * TROWB);
                uint32_t t0, t1, t2, t3;
                ldm4(base + 2 * TILE_B + off, t0, t1, t2, t3);
                bH[nb * 2][0] = t0; bH[nb * 2][1] = t1;
                bH[nb * 2 + 1][0] = t2; bH[nb * 2 + 1][1] = t3;
                ldm4(base + 3 * TILE_B + off, t0, t1, t2, t3);
                bL[nb * 2][0] = t0; bL[nb * 2][1] = t1;
                bL[nb * 2 + 1][0] = t2; bL[nb * 2 + 1][1] = t3;
            }
            uint32_t a[4];
#pragma unroll
            for (int mi = 0; mi < 4; mi++) {
                uint32_t off = offA + koff + (uint32_t)(mi * 16 * TROWB);
                ldm4(base + off, a[0], a[1], a[2], a[3]);
#pragma unroll
                for (int nj = 0; nj < 4; nj++) {
                    mma16816(acc[mi * 4 + nj], a, bH[nj]);
                    mma16816(acc[mi * 4 + nj], a, bL[nj]);
                }
                ldm4(base + TILE_B + off, a[0], a[1], a[2], a[3]);
#pragma unroll
                for (int nj = 0; nj < 4; nj++)
                    mma16816(acc[mi * 4 + nj], a, bH[nj]);
            }
        }
        __syncthreads();   // protect the stage being prefetched next iteration
    }

    // epilogue (proven)
    unsigned short* oH = (outp >= 0) ? pairH(outp) : nullptr;
    unsigned short* oL = (outp >= 0) ? pairL(outp) : nullptr;
    float* f32d = (f32sel == 0) ? g_hf0 : (f32sel == 1) ? g_hf1 : cext;
#pragma unroll
    for (int mi = 0; mi < 4; mi++) {
#pragma unroll
        for (int nj = 0; nj < 4; nj++) {
            float* c = acc[mi * 4 + nj];
            int col = bn + wn * 32 + nj * 8 + (lane & 3) * 2;
            float bi0 = bias[col], bi1 = bias[col + 1];
#pragma unroll
            for (int half = 0; half < 2; half++) {
                int r = bm + wm * 64 + mi * 16 + (lane >> 2) + half * 8;
                if (r >= NN) continue;
                float v0 = c[half * 2] + bi0;
                float v1 = c[half * 2 + 1] + bi1;
                if (relu) { v0 = fmaxf(v0, 0.f); v1 = fmaxf(v1, 0.f); }
                if (oH) {
                    __nv_bfloat16 h0 = __float2bfloat16_rn(v0);
                    __nv_bfloat16 h1 = __float2bfloat16_rn(v1);
                    unsigned short l0 = __bfloat16_as_ushort(
                        __float2bfloat16_rn(v0 - __bfloat162float(h0)));
                    unsigned short l1 = __bfloat16_as_ushort(
                        __float2bfloat16_rn(v1 - __bfloat162float(h1)));
                    size_t base = (size_t)r * D + col;
                    *(ushort2*)(oH + base) =
                        make_ushort2(__bfloat16_as_ushort(h0), __bfloat16_as_ushort(h1));
                    *(ushort2*)(oL + base) = make_ushort2(l0, l1);
                }
                if (f32sel >= 0)
                    *(float2*)(f32d + (size_t)r * ldc + col) = make_float2(v0, v1);
            }
        }
    }
}

// ---------------- row-wise log_softmax over 128 cols, in place ----------------
__global__ void k_lsm(float* __restrict__ out) {
    int r = blockIdx.x;
    int t = threadIdx.x;
    float v = out[(size_t)r * DOUT + t];
    __shared__ float smax[4], ssum[4];
    float m = v;
#pragma unroll
    for (int o = 16; o; o >>= 1) m = fmaxf(m, __shfl_xor_sync(0xffffffffu, m, o));
    if ((t & 31) == 0) smax[t >> 5] = m;
    __syncthreads();
    float mm = fmaxf(fmaxf(smax[0], smax[1]), fmaxf(smax[2], smax[3]));
    float e = expf(v - mm);
    float sum = e;
#pragma unroll
    for (int o = 16; o; o >>= 1) sum += __shfl_xor_sync(0xffffffffu, sum, o);
    if ((t & 31) == 0) ssum[t >> 5] = sum;
    __syncthreads();
    float tot = ssum[0] + ssum[1] + ssum[2] + ssum[3];
    out[(size_t)r * DOUT + t] = v - mm - logf(tot);
}

// ---------------- launch: kernel launches ONLY ----------------
extern "C" void kernel_launch(void* const* d_in, const int* in_sizes, int n_in,
                              void* d_out, int out_size) {
    const float* x  = (const float*)d_in[0];
    const void*  ei = d_in[1];
    const float* wl = (const float*)d_in[2];
    const float* bl = (const float*)d_in[3];
    const float* wr = (const float*)d_in[4];
    const float* w1 = (const float*)d_in[5];
    const float* b1 = (const float*)d_in[6];
    const float* w2 = (const float*)d_in[7];
    const float* b2 = (const float*)d_in[8];
    float* out = (float*)d_out;

    // enable 80 KB dynamic smem for k_mma (idempotent; not a stream op)
    cudaFuncSetAttribute(k_mma, cudaFuncAttributeMaxDynamicSharedMemorySize, SMEM_DYN);

    // operand prep
    k_split_x<<<(NN * D / 4 + 255) / 256, 256>>>(x);
    for (int l = 0; l < 3; l++) {
        k_split_w<<<(D * D + 255) / 256, 256>>>(wl + (size_t)l * D * D, D, D, l * 65536);
        k_split_w<<<(D * D + 255) / 256, 256>>>(wr + (size_t)l * D * D, D, D, (3 + l) * 65536);
    }
    k_split_w<<<(D * D + 255) / 256, 256>>>(w1, D, D, 6 * 65536);
    k_split_w<<<(D * DOUT + 255) / 256, 256>>>(w2, D, DOUT, 7 * 65536);

    // CSR by dst
    k_detect<<<1, 512>>>((const int*)ei);
    k_zero_deg<<<(NN + 255) / 256, 256>>>();
    k_hist<<<(NE + 255) / 256, 256>>>(ei);
    k_scan1<<<SCAN_B, 1024>>>();
    k_scan2<<<1, 1>>>();
    k_scan3<<<(NN + 255) / 256, 256>>>();
    k_fill<<<(NE + 255) / 256, 256>>>(ei);

    dim3 g2((NN + 127) / 128, 2);
    dim3 g1((NN + 127) / 128, 1);

    // layer 0: agg(x); h0 = relu(agg@wl0 + x@wr0 + bl0)   (pair + fp32 copy -> g_hf0)
    k_agg<<<4096, 256>>>(x, 3);
    k_mma<<<g2, 256, SMEM_DYN>>>(3, 0, 1, 1, 0, nullptr, 0 * 65536, 3 * 65536, bl + 0 * D, 1, D);
    // layer 1: agg(h0); h1 = relu(...)                    (pair + fp32 copy -> g_hf1)
    k_agg<<<4096, 256>>>(nullptr, 0);
    k_mma<<<g2, 256, SMEM_DYN>>>(3, 1, 1, 2, 1, nullptr, 1 * 65536, 4 * 65536, bl + 1 * D, 1, D);
    // layer 2: agg(h1); h0 = relu(...)                    (pair only)
    k_agg<<<4096, 256>>>(nullptr, 1);
    k_mma<<<g2, 256, SMEM_DYN>>>(3, 2, 1, 1, -1, nullptr, 2 * 65536, 5 * 65536, bl + 2 * D, 1, D);
    // post_mp: z = h0@w1 + b1 (pair -> agg bufs); out = z@w2 + b2 (fp32 ext)
    k_mma<<<g2, 256, SMEM_DYN>>>(1, 1, 0, 3, -1, nullptr, 6 * 65536, 0, b1, 0, D);
    k_mma<<<g1, 256, SMEM_DYN>>>(3, 3, 0, -1, 2, out, 7 * 65536, 0, b2, 0, DOUT);
    k_lsm<<<NN, 128>>>(out);
}

// round 9
// speedup vs baseline: 1.1253x; 1.0512x over previous
#include <cuda_runtime.h>
#include <cuda_fp16.h>
#include <cstdint>

#define NN 50000
#define NE 800000
#define D 256
#define DOUT 128
#define SCAN_B 49   // ceil(50000/1024)

// ---------------- device scratch (static: no allocation allowed) ----------------
// fp16 hi/lo pairs (hi+lo reconstructs fp32 to ~2^-23)
__device__ unsigned short g_xH[NN * D],   g_xL[NN * D];
__device__ unsigned short g_h0H[NN * D],  g_h0L[NN * D];
__device__ unsigned short g_h1H[NN * D],  g_h1L[NN * D];
__device__ unsigned short g_aggH[NN * D], g_aggL[NN * D];
__device__ unsigned short g_wt[8 * 65536];   // transposed single-fp16 weights
__device__ float g_deginv[NN];
__device__ int   g_deg[NN];
__device__ int   g_rowptr[NN + 1];
__device__ int   g_cursor[NN];
__device__ int   g_col[NE];
__device__ int   g_bsum[SCAN_B];
__device__ int   g_is64;

// pair ids: 0 -> x, 1 -> h0, 2 -> h1, 3 -> agg/z
__device__ __forceinline__ unsigned short* pairH(int id) {
    if (id == 0) return g_xH;
    if (id == 1) return g_h0H;
    if (id == 2) return g_h1H;
    return g_aggH;
}
__device__ __forceinline__ unsigned short* pairL(int id) {
    if (id == 0) return g_xL;
    if (id == 1) return g_h0L;
    if (id == 2) return g_h1L;
    return g_aggL;
}

__device__ __forceinline__ int edge_at(const void* ei, int word) {
    if (g_is64) return (int)((const long long*)ei)[word];
    return ((const int*)ei)[word];
}

__device__ __forceinline__ uint32_t smem_u32(const void* p) {
    uint32_t a;
    asm("{ .reg .u64 t; cvta.to.shared.u64 t, %1; cvt.u32.u64 %0, t; }" : "=r"(a) : "l"(p));
    return a;
}
__device__ __forceinline__ void ldm4(uint32_t addr, uint32_t& r0, uint32_t& r1,
                                     uint32_t& r2, uint32_t& r3) {
    asm volatile("ldmatrix.sync.aligned.m8n8.x4.shared.b16 {%0,%1,%2,%3}, [%4];"
                 : "=r"(r0), "=r"(r1), "=r"(r2), "=r"(r3) : "r"(addr));
}
__device__ __forceinline__ void mma16816(float* c, const uint32_t* a, const uint32_t* b) {
    asm volatile("mma.sync.aligned.m16n8k16.row.col.f32.f16.f16.f32 "
                 "{%0,%1,%2,%3}, {%4,%5,%6,%7}, {%8,%9}, {%0,%1,%2,%3};"
                 : "+f"(c[0]), "+f"(c[1]), "+f"(c[2]), "+f"(c[3])
                 : "r"(a[0]), "r"(a[1]), "r"(a[2]), "r"(a[3]), "r"(b[0]), "r"(b[1]));
}
__device__ __forceinline__ void cpa16(uint32_t dst, const void* src, int valid) {
    asm volatile("cp.async.cg.shared.global [%0], [%1], 16, %2;"
                 :: "r"(dst), "l"(src), "r"(valid ? 16 : 0));
}
#define CP_COMMIT() asm volatile("cp.async.commit_group;" ::: "memory")
#define CP_WAIT1()  asm volatile("cp.async.wait_group 1;" ::: "memory")
#define CP_WAIT0()  asm volatile("cp.async.wait_group 0;" ::: "memory")

__device__ __forceinline__ void split16(float v, unsigned short& h, unsigned short& l) {
    __half hh = __float2half_rn(v);
    __half ll = __float2half_rn(v - __half2float(hh));
    h = __half_as_ushort(hh);
    l = __half_as_ushort(ll);
}

// ---------------- splits ----------------
__global__ void k_split_x(const float* __restrict__ x) {
    int i = (blockIdx.x * blockDim.x + threadIdx.x) * 4;
    if (i >= NN * D) return;
#pragma unroll
    for (int j = 0; j < 4; j++) split16(x[i + j], g_xH[i + j], g_xL[i + j]);
}

// all weights, transposed, single fp16: g_wt[m*65536 + n*256 + k]
__global__ void k_split_wall(const float* __restrict__ wl, const float* __restrict__ wr,
                             const float* __restrict__ w1, const float* __restrict__ w2) {
    int idx = blockIdx.x * blockDim.x + threadIdx.x;
    if (idx < 7 * 65536) {
        int m = idx >> 16, t = idx & 65535;
        const float* src = (m < 3) ? (wl + (size_t)m * 65536)
                         : (m < 6) ? (wr + (size_t)(m - 3) * 65536) : w1;
        int k = t >> 8, n = t & 255;
        g_wt[m * 65536 + n * 256 + k] = __half_as_ushort(__float2half_rn(src[t]));
    } else if (idx < 7 * 65536 + D * DOUT) {
        int t = idx - 7 * 65536;
        int k = t >> 7, n = t & 127;
        g_wt[7 * 65536 + n * 256 + k] = __half_as_ushort(__float2half_rn(w2[t]));
    }
}

// ---------------- dtype probe ----------------
__global__ void k_detect(const int* __restrict__ ei32) {
    __shared__ int nz;
    if (threadIdx.x == 0) nz = 0;
    __syncthreads();
    if (ei32[2 * threadIdx.x + 1] != 0) atomicOr(&nz, 1);
    __syncthreads();
    if (threadIdx.x == 0) g_is64 = nz ? 0 : 1;
}

// ---------------- CSR build ----------------
__global__ void k_zero_deg() {
    int i = blockIdx.x * blockDim.x + threadIdx.x;
    if (i < NN) g_deg[i] = 0;
}
__global__ void k_hist(const void* __restrict__ ei) {
    int e = blockIdx.x * blockDim.x + threadIdx.x;
    if (e < NE) {
        unsigned d = (unsigned)edge_at(ei, NE + e);
        if (d < NN) atomicAdd(&g_deg[d], 1);
    }
}
__global__ void k_scan1() {
    __shared__ int s[1024];
    int t = threadIdx.x;
    int i = blockIdx.x * 1024 + t;
    int v = (i < NN) ? g_deg[i] : 0;
    s[t] = v;
    __syncthreads();
    for (int o = 1; o < 1024; o <<= 1) {
        int a = (t >= o) ? s[t - o] : 0;
        __syncthreads();
        s[t] += a;
        __syncthreads();
    }
    if (i < NN) g_rowptr[i] = s[t] - v;
    if (t == 1023) g_bsum[blockIdx.x] = s[1023];
}
__global__ void k_scan2() {
    int run = 0;
    for (int b = 0; b < SCAN_B; b++) { int t = g_bsum[b]; g_bsum[b] = run; run += t; }
}
__global__ void k_scan3() {
    int i = blockIdx.x * blockDim.x + threadIdx.x;
    if (i < NN) {
        int rp = g_rowptr[i] + g_bsum[i >> 10];
        g_rowptr[i] = rp;
        g_cursor[i] = rp;
        int dg = g_deg[i];
        g_deginv[i] = 1.0f / (float)(dg > 0 ? dg : 1);
    }
    if (i == 0) g_rowptr[NN] = NE;
}
__global__ void k_fill(const void* __restrict__ ei) {
    int e = blockIdx.x * blockDim.x + threadIdx.x;
    if (e < NE) {
        unsigned d = (unsigned)edge_at(ei, NE + e);
        unsigned s = (unsigned)edge_at(ei, e);
        if (d < NN && s < NN) {
            int pos = atomicAdd(&g_cursor[d], 1);
            g_col[pos] = (int)s;
        }
    }
}

// ---------------- mean aggregation over a pair input -> agg pair ----------------
__global__ void k_agg(int src_id) {
    const unsigned short* __restrict__ HH = pairH(src_id);
    const unsigned short* __restrict__ LL = pairL(src_id);
    __shared__ int sc[256];
    int t = threadIdx.x;
    for (int r = blockIdx.x; r < NN; r += gridDim.x) {
        int beg = g_rowptr[r], end = g_rowptr[r + 1];
        float acc = 0.f;
        for (int base = beg; base < end; base += 256) {
            int cnt = min(256, end - base);
            __syncthreads();
            if (t < cnt) sc[t] = g_col[base + t];
            __syncthreads();
            int i = 0;
            for (; i + 4 <= cnt; i += 4) {
                size_t i0 = (size_t)sc[i]     * D + t;
                size_t i1 = (size_t)sc[i + 1] * D + t;
                size_t i2 = (size_t)sc[i + 2] * D + t;
                size_t i3 = (size_t)sc[i + 3] * D + t;
                float a0 = __half2float(__ushort_as_half(HH[i0])) + __half2float(__ushort_as_half(LL[i0]));
                float a1 = __half2float(__ushort_as_half(HH[i1])) + __half2float(__ushort_as_half(LL[i1]));
                float a2 = __half2float(__ushort_as_half(HH[i2])) + __half2float(__ushort_as_half(LL[i2]));
                float a3 = __half2float(__ushort_as_half(HH[i3])) + __half2float(__ushort_as_half(LL[i3]));
                acc += (a0 + a1) + (a2 + a3);
            }
            for (; i < cnt; i++) {
                size_t i0 = (size_t)sc[i] * D + t;
                acc += __half2float(__ushort_as_half(HH[i0])) + __half2float(__ushort_as_half(LL[i0]));
            }
        }
        float v = acc * g_deginv[r];
        split16(v, g_aggH[(size_t)r * D + t], g_aggL[(size_t)r * D + t]);
    }
}

// ---------------- fp16 A-split tensor-core GEMM, 2-stage cp.async, K-chunk 32 ----------------
// C[128x128 tile] = sum_src (AH+AL)@B^T  (2 products), fused bias(+relu).
// Tiles AH/AL/B: 128 rows x 32 fp16, 80 B padded rows (conflict-free ldmatrix).
#define TROWB   80
#define TILE_B  (128 * TROWB)       // 10240
#define STAGE_B (3 * TILE_B)        // 30720
#define SMEM_DYN (2 * STAGE_B)      // 61440 (60 KB)

__global__ __launch_bounds__(256, 2)
void k_mma(int a1id, int a2id, int dual, int outp,
           float* __restrict__ cext, int woff1, int woff2,
           const float* __restrict__ bias, int relu, int ldc) {
    extern __shared__ __align__(16) unsigned char sT[];
    uint32_t sb = smem_u32(sT);
    int tid = threadIdx.x;
    int lane = tid & 31;
    int wid = tid >> 5;
    int wm = wid & 1;        // 2 warp-rows (64 rows)
    int wn = wid >> 1;       // 4 warp-cols (32 cols)
    int bm = blockIdx.x * 128;
    int bn = blockIdx.y * 128;

    const unsigned short* pAH[2] = { pairH(a1id), pairH(a2id) };
    const unsigned short* pAL[2] = { pairL(a1id), pairL(a2id) };
    const unsigned short* pB[2]  = { g_wt + woff1, g_wt + woff2 };

    float acc[16][4];
#pragma unroll
    for (int i = 0; i < 16; i++)
#pragma unroll
        for (int j = 0; j < 4; j++) acc[i][j] = 0.f;

    // loader: 128 rows x 32 fp16 (64 B) per tile; thread -> (row, 16B segment pair)
    int lrow = tid >> 1, s0 = tid & 1;
    int gr = bm + lrow;
    int av = gr < NN;
    size_t arow = (size_t)(av ? gr : 0) * D;
    size_t brow = (size_t)(bn + lrow) * D;
    uint32_t drow = sb + (uint32_t)(lrow * TROWB);

    // ldmatrix lane-address components (proven mapping, stride 80)
    int grp = lane >> 3, lr = lane & 7;
    int a_r = wm * 64 + ((grp & 1) << 3) + lr;
    int a_c = (grp & 2) ? 8 : 0;
    int b_r = wn * 32 + ((grp & 2) << 2) + lr;
    int b_c = (grp & 1) << 3;
    uint32_t offA = (uint32_t)(a_r * TROWB + a_c * 2);
    uint32_t offB = (uint32_t)(b_r * TROWB + b_c * 2);

    int NIT = dual ? 16 : 8;

    // prologue: iteration 0 -> stage 0
#pragma unroll
    for (int j2 = 0; j2 < 2; j2++) {
        int seg = s0 + 2 * j2;
        uint32_t d = drow + (uint32_t)(seg * 16);
        size_t go = (size_t)(seg * 8);
        cpa16(d,              pAH[0] + arow + go, av);
        cpa16(d + TILE_B,     pAL[0] + arow + go, av);
        cpa16(d + 2 * TILE_B, pB[0]  + brow + go, 1);
    }
    CP_COMMIT();

    for (int it = 0; it < NIT; it++) {
        if (it + 1 < NIT) {
            int s = (it + 1) >> 3, kc = (it + 1) & 7;
            uint32_t stg = (uint32_t)(((it + 1) & 1) * STAGE_B);
#pragma unroll
            for (int j2 = 0; j2 < 2; j2++) {
                int seg = s0 + 2 * j2;
                uint32_t d = drow + stg + (uint32_t)(seg * 16);
                size_t go = (size_t)(kc * 32 + seg * 8);
                cpa16(d,              pAH[s] + arow + go, av);
                cpa16(d + TILE_B,     pAL[s] + arow + go, av);
                cpa16(d + 2 * TILE_B, pB[s]  + brow + go, 1);
            }
            CP_COMMIT();
            CP_WAIT1();
        } else {
            CP_WAIT0();
        }
        __syncthreads();

        uint32_t base = sb + (uint32_t)((it & 1) * STAGE_B);
#pragma unroll
        for (int kk = 0; kk < 32; kk += 16) {
            uint32_t koff = (uint32_t)(kk * 2);
            uint32_t b[4][2];
#pragma unroll
            for (int nb = 0; nb < 2; nb++) {
                uint32_t off = offB + koff + (uint32_t)(nb * 16 * TROWB);
                uint32_t t0, t1, t2, t3;
                ldm4(base + 2 * TILE_B + off, t0, t1, t2, t3);
                b[nb * 2][0] = t0; b[nb * 2][1] = t1;
                b[nb * 2 + 1][0] = t2; b[nb * 2 + 1][1] = t3;
            }
            uint32_t a[4];
#pragma unroll
            for (int mi = 0; mi < 4; mi++) {
                uint32_t off = offA + koff + (uint32_t)(mi * 16 * TROWB);
                ldm4(base + off, a[0], a[1], a[2], a[3]);
#pragma unroll
                for (int nj = 0; nj < 4; nj++)
                    mma16816(acc[mi * 4 + nj], a, b[nj]);
                ldm4(base + TILE_B + off, a[0], a[1], a[2], a[3]);
#pragma unroll
                for (int nj = 0; nj < 4; nj++)
                    mma16816(acc[mi * 4 + nj], a, b[nj]);
            }
        }
        __syncthreads();   // protect the stage being prefetched next iteration
    }

    // epilogue
    unsigned short* oH = (outp >= 0) ? pairH(outp) : nullptr;
    unsigned short* oL = (outp >= 0) ? pairL(outp) : nullptr;
#pragma unroll
    for (int mi = 0; mi < 4; mi++) {
#pragma unroll
        for (int nj = 0; nj < 4; nj++) {
            float* c = acc[mi * 4 + nj];
            int col = bn + wn * 32 + nj * 8 + (lane & 3) * 2;
            float bi0 = bias[col], bi1 = bias[col + 1];
#pragma unroll
            for (int half = 0; half < 2; half++) {
                int r = bm + wm * 64 + mi * 16 + (lane >> 2) + half * 8;
                if (r >= NN) continue;
                float v0 = c[half * 2] + bi0;
                float v1 = c[half * 2 + 1] + bi1;
                if (relu) { v0 = fmaxf(v0, 0.f); v1 = fmaxf(v1, 0.f); }
                if (oH) {
                    unsigned short h0, l0, h1, l1;
                    split16(v0, h0, l0);
                    split16(v1, h1, l1);
                    size_t base = (size_t)r * D + col;
                    *(ushort2*)(oH + base) = make_ushort2(h0, h1);
                    *(ushort2*)(oL + base) = make_ushort2(l0, l1);
                } else {
                    *(float2*)(cext + (size_t)r * ldc + col) = make_float2(v0, v1);
                }
            }
        }
    }
}

// ---------------- row-wise log_softmax over 128 cols, in place ----------------
__global__ void k_lsm(float* __restrict__ out) {
    int r = blockIdx.x;
    int t = threadIdx.x;
    float v = out[(size_t)r * DOUT + t];
    __shared__ float smax[4], ssum[4];
    float m = v;
#pragma unroll
    for (int o = 16; o; o >>= 1) m = fmaxf(m, __shfl_xor_sync(0xffffffffu, m, o));
    if ((t & 31) == 0) smax[t >> 5] = m;
    __syncthreads();
    float mm = fmaxf(fmaxf(smax[0], smax[1]), fmaxf(smax[2], smax[3]));
    float e = expf(v - mm);
    float sum = e;
#pragma unroll
    for (int o = 16; o; o >>= 1) sum += __shfl_xor_sync(0xffffffffu, sum, o);
    if ((t & 31) == 0) ssum[t >> 5] = sum;
    __syncthreads();
    float tot = ssum[0] + ssum[1] + ssum[2] + ssum[3];
    out[(size_t)r * DOUT + t] = v - mm - logf(tot);
}

// ---------------- launch: kernel launches ONLY ----------------
extern "C" void kernel_launch(void* const* d_in, const int* in_sizes, int n_in,
                              void* d_out, int out_size) {
    const float* x  = (const float*)d_in[0];
    const void*  ei = d_in[1];
    const float* wl = (const float*)d_in[2];
    const float* bl = (const float*)d_in[3];
    const float* wr = (const float*)d_in[4];
    const float* w1 = (const float*)d_in[5];
    const float* b1 = (const float*)d_in[6];
    const float* w2 = (const float*)d_in[7];
    const float* b2 = (const float*)d_in[8];
    float* out = (float*)d_out;

    cudaFuncSetAttribute(k_mma, cudaFuncAttributeMaxDynamicSharedMemorySize, SMEM_DYN);

    // operand prep
    k_split_x<<<(NN * D / 4 + 255) / 256, 256>>>(x);
    k_split_wall<<<(7 * 65536 + D * DOUT + 255) / 256, 256>>>(wl, wr, w1, w2);

    // CSR by dst
    k_detect<<<1, 512>>>((const int*)ei);
    k_zero_deg<<<(NN + 255) / 256, 256>>>();
    k_hist<<<(NE + 255) / 256, 256>>>(ei);
    k_scan1<<<SCAN_B, 1024>>>();
    k_scan2<<<1, 1>>>();
    k_scan3<<<(NN + 255) / 256, 256>>>();
    k_fill<<<(NE + 255) / 256, 256>>>(ei);

    dim3 g2((NN + 127) / 128, 2);
    dim3 g1((NN + 127) / 128, 1);

    // layer 0: agg(x pair); h0 = relu(agg@wl0 + x@wr0 + bl0)
    k_agg<<<4096, 256>>>(0);
    k_mma<<<g2, 256, SMEM_DYN>>>(3, 0, 1, 1, nullptr, 0 * 65536, 3 * 65536, bl + 0 * D, 1, D);
    // layer 1: agg(h0); h1 = relu(...)
    k_agg<<<4096, 256>>>(1);
    k_mma<<<g2, 256, SMEM_DYN>>>(3, 1, 1, 2, nullptr, 1 * 65536, 4 * 65536, bl + 1 * D, 1, D);
    // layer 2: agg(h1); h0 pair = relu(...)  (h0 dead after layer-1 GEMM)
    k_agg<<<4096, 256>>>(2);
    k_mma<<<g2, 256, SMEM_DYN>>>(3, 2, 1, 1, nullptr, 2 * 65536, 5 * 65536, bl + 2 * D, 1, D);
    // post_mp: z(pair 3) = h(pair 1)@w1 + b1 ; out = z@w2 + b2
    k_mma<<<g2, 256, SMEM_DYN>>>(1, 1, 0, 3, nullptr, 6 * 65536, 0, b1, 0, D);
    k_mma<<<g1, 256, SMEM_DYN>>>(3, 3, 0, -1, out, 7 * 65536, 0, b2, 0, DOUT);
    k_lsm<<<NN, 128>>>(out);
}

// round 10
// speedup vs baseline: 1.7083x; 1.5180x over previous
#include <cuda_runtime.h>
#include <cuda_fp16.h>
#include <cstdint>

#define NN 50000
#define NE 800000
#define D 256
#define DOUT 128
#define SCAN_B 49   // ceil(50000/1024)

// ---------------- device scratch (static: no allocation allowed) ----------------
__device__ unsigned short g_x16[NN * D];     // fp16 activations
__device__ unsigned short g_h0[NN * D];
__device__ unsigned short g_h1[NN * D];
__device__ unsigned short g_agg[NN * D];     // agg / z buffer
__device__ unsigned short g_wt[8 * 65536];   // transposed fp16 weights
__device__ float g_deginv[NN];
__device__ int   g_deg[NN];
__device__ int   g_rowptr[NN + 1];
__device__ int   g_cursor[NN];
__device__ int   g_col[NE];
__device__ int   g_bsum[SCAN_B];
__device__ int   g_is64;

// ids: 0 -> x, 1 -> h0, 2 -> h1, 3 -> agg/z
__device__ __forceinline__ unsigned short* bufp(int id) {
    if (id == 0) return g_x16;
    if (id == 1) return g_h0;
    if (id == 2) return g_h1;
    return g_agg;
}

__device__ __forceinline__ int edge_at(const void* ei, int word) {
    if (g_is64) return (int)((const long long*)ei)[word];
    return ((const int*)ei)[word];
}

__device__ __forceinline__ uint32_t smem_u32(const void* p) {
    uint32_t a;
    asm("{ .reg .u64 t; cvta.to.shared.u64 t, %1; cvt.u32.u64 %0, t; }" : "=r"(a) : "l"(p));
    return a;
}
__device__ __forceinline__ void ldm4(uint32_t addr, uint32_t& r0, uint32_t& r1,
                                     uint32_t& r2, uint32_t& r3) {
    asm volatile("ldmatrix.sync.aligned.m8n8.x4.shared.b16 {%0,%1,%2,%3}, [%4];"
                 : "=r"(r0), "=r"(r1), "=r"(r2), "=r"(r3) : "r"(addr));
}
__device__ __forceinline__ void mma16816(float* c, const uint32_t* a, const uint32_t* b) {
    asm volatile("mma.sync.aligned.m16n8k16.row.col.f32.f16.f16.f32 "
                 "{%0,%1,%2,%3}, {%4,%5,%6,%7}, {%8,%9}, {%0,%1,%2,%3};"
                 : "+f"(c[0]), "+f"(c[1]), "+f"(c[2]), "+f"(c[3])
                 : "r"(a[0]), "r"(a[1]), "r"(a[2]), "r"(a[3]), "r"(b[0]), "r"(b[1]));
}
__device__ __forceinline__ void cpa16(uint32_t dst, const void* src, int valid) {
    asm volatile("cp.async.cg.shared.global [%0], [%1], 16, %2;"
                 :: "r"(dst), "l"(src), "r"(valid ? 16 : 0));
}
#define CP_COMMIT() asm volatile("cp.async.commit_group;" ::: "memory")
#define CP_WAIT1()  asm volatile("cp.async.wait_group 1;" ::: "memory")
#define CP_WAIT0()  asm volatile("cp.async.wait_group 0;" ::: "memory")

// ---------------- splits ----------------
__global__ void k_split_x(const float* __restrict__ x) {
    int i = (blockIdx.x * blockDim.x + threadIdx.x) * 4;
    if (i >= NN * D) return;
#pragma unroll
    for (int j = 0; j < 4; j++)
        g_x16[i + j] = __half_as_ushort(__float2half_rn(x[i + j]));
}

// all weights, transposed fp16: g_wt[m*65536 + n*256 + k]
__global__ void k_split_wall(const float* __restrict__ wl, const float* __restrict__ wr,
                             const float* __restrict__ w1, const float* __restrict__ w2) {
    int idx = blockIdx.x * blockDim.x + threadIdx.x;
    if (idx < 7 * 65536) {
        int m = idx >> 16, t = idx & 65535;
        const float* src = (m < 3) ? (wl + (size_t)m * 65536)
                         : (m < 6) ? (wr + (size_t)(m - 3) * 65536) : w1;
        int k = t >> 8, n = t & 255;
        g_wt[m * 65536 + n * 256 + k] = __half_as_ushort(__float2half_rn(src[t]));
    } else if (idx < 7 * 65536 + D * DOUT) {
        int t = idx - 7 * 65536;
        int k = t >> 7, n = t & 127;
        g_wt[7 * 65536 + n * 256 + k] = __half_as_ushort(__float2half_rn(w2[t]));
    }
}

// ---------------- dtype probe ----------------
__global__ void k_detect(const int* __restrict__ ei32) {
    __shared__ int nz;
    if (threadIdx.x == 0) nz = 0;
    __syncthreads();
    if (ei32[2 * threadIdx.x + 1] != 0) atomicOr(&nz, 1);
    __syncthreads();
    if (threadIdx.x == 0) g_is64 = nz ? 0 : 1;
}

// ---------------- CSR build ----------------
__global__ void k_zero_deg() {
    int i = blockIdx.x * blockDim.x + threadIdx.x;
    if (i < NN) g_deg[i] = 0;
}
__global__ void k_hist(const void* __restrict__ ei) {
    int e = blockIdx.x * blockDim.x + threadIdx.x;
    if (e < NE) {
        unsigned d = (unsigned)edge_at(ei, NE + e);
        if (d < NN) atomicAdd(&g_deg[d], 1);
    }
}
__global__ void k_scan1() {
    __shared__ int s[1024];
    int t = threadIdx.x;
    int i = blockIdx.x * 1024 + t;
    int v = (i < NN) ? g_deg[i] : 0;
    s[t] = v;
    __syncthreads();
    for (int o = 1; o < 1024; o <<= 1) {
        int a = (t >= o) ? s[t - o] : 0;
        __syncthreads();
        s[t] += a;
        __syncthreads();
    }
    if (i < NN) g_rowptr[i] = s[t] - v;
    if (t == 1023) g_bsum[blockIdx.x] = s[1023];
}
__global__ void k_scan2() {
    int run = 0;
    for (int b = 0; b < SCAN_B; b++) { int t = g_bsum[b]; g_bsum[b] = run; run += t; }
}
__global__ void k_scan3() {
    int i = blockIdx.x * blockDim.x + threadIdx.x;
    if (i < NN) {
        int rp = g_rowptr[i] + g_bsum[i >> 10];
        g_rowptr[i] = rp;
        g_cursor[i] = rp;
        int dg = g_deg[i];
        g_deginv[i] = 1.0f / (float)(dg > 0 ? dg : 1);
    }
    if (i == 0) g_rowptr[NN] = NE;
}
__global__ void k_fill(const void* __restrict__ ei) {
    int e = blockIdx.x * blockDim.x + threadIdx.x;
    if (e < NE) {
        unsigned d = (unsigned)edge_at(ei, NE + e);
        unsigned s = (unsigned)edge_at(ei, e);
        if (d < NN && s < NN) {
            int pos = atomicAdd(&g_cursor[d], 1);
            g_col[pos] = (int)s;
        }
    }
}

// ---------------- mean aggregation (fp16 in/out, fp32 accumulate) ----------------
__global__ void k_agg(int src_id) {
    const unsigned short* __restrict__ H = bufp(src_id);
    __shared__ int sc[256];
    int t = threadIdx.x;
    for (int r = blockIdx.x; r < NN; r += gridDim.x) {
        int beg = g_rowptr[r], end = g_rowptr[r + 1];
        float acc = 0.f;
        for (int base = beg; base < end; base += 256) {
            int cnt = min(256, end - base);
            __syncthreads();
            if (t < cnt) sc[t] = g_col[base + t];
            __syncthreads();
            int i = 0;
            for (; i + 4 <= cnt; i += 4) {
                float a0 = __half2float(__ushort_as_half(H[(size_t)sc[i]     * D + t]));
                float a1 = __half2float(__ushort_as_half(H[(size_t)sc[i + 1] * D + t]));
                float a2 = __half2float(__ushort_as_half(H[(size_t)sc[i + 2] * D + t]));
                float a3 = __half2float(__ushort_as_half(H[(size_t)sc[i + 3] * D + t]));
                acc += (a0 + a1) + (a2 + a3);
            }
            for (; i < cnt; i++)
                acc += __half2float(__ushort_as_half(H[(size_t)sc[i] * D + t]));
        }
        g_agg[(size_t)r * D + t] =
            __half_as_ushort(__float2half_rn(acc * g_deginv[r]));
    }
}

// ---------------- fp16 tensor-core GEMM, 2-stage cp.async, K-chunk 32 ----------------
// C[128x128 tile] = sum_src A@B^T, fused bias(+relu).
// Tiles A/B: 128 rows x 32 fp16, 80 B padded rows (conflict-free ldmatrix).
#define TROWB   80
#define TILE_B  (128 * TROWB)       // 10240
#define STAGE_B (2 * TILE_B)        // 20480
#define SMEM_DYN (2 * STAGE_B)      // 40960 (40 KB)

__global__ __launch_bounds__(256, 2)
void k_mma(int a1id, int a2id, int dual, int outp,
           float* __restrict__ cext, int woff1, int woff2,
           const float* __restrict__ bias, int relu, int ldc) {
    extern __shared__ __align__(16) unsigned char sT[];
    uint32_t sb = smem_u32(sT);
    int tid = threadIdx.x;
    int lane = tid & 31;
    int wid = tid >> 5;
    int wm = wid & 1;        // 2 warp-rows (64 rows)
    int wn = wid >> 1;       // 4 warp-cols (32 cols)
    int bm = blockIdx.x * 128;
    int bn = blockIdx.y * 128;

    const unsigned short* pA[2] = { bufp(a1id), bufp(a2id) };
    const unsigned short* pB[2] = { g_wt + woff1, g_wt + woff2 };

    float acc[16][4];
#pragma unroll
    for (int i = 0; i < 16; i++)
#pragma unroll
        for (int j = 0; j < 4; j++) acc[i][j] = 0.f;

    // loader: 128 rows x 32 fp16 (64 B) per tile; thread -> (row, 16B segment pair)
    int lrow = tid >> 1, s0 = tid & 1;
    int gr = bm + lrow;
    int av = gr < NN;
    size_t arow = (size_t)(av ? gr : 0) * D;
    size_t brow = (size_t)(bn + lrow) * D;
    uint32_t drow = sb + (uint32_t)(lrow * TROWB);

    // ldmatrix lane-address components (proven mapping, stride 80)
    int grp = lane >> 3, lr = lane & 7;
    int a_r = wm * 64 + ((grp & 1) << 3) + lr;
    int a_c = (grp & 2) ? 8 : 0;
    int b_r = wn * 32 + ((grp & 2) << 2) + lr;
    int b_c = (grp & 1) << 3;
    uint32_t offA = (uint32_t)(a_r * TROWB + a_c * 2);
    uint32_t offB = (uint32_t)(b_r * TROWB + b_c * 2);

    int NIT = dual ? 16 : 8;

    // prologue: iteration 0 -> stage 0
#pragma unroll
    for (int j2 = 0; j2 < 2; j2++) {
        int seg = s0 + 2 * j2;
        uint32_t d = drow + (uint32_t)(seg * 16);
        size_t go = (size_t)(seg * 8);
        cpa16(d,          pA[0] + arow + go, av);
        cpa16(d + TILE_B, pB[0] + brow + go, 1);
    }
    CP_COMMIT();

    for (int it = 0; it < NIT; it++) {
        if (it + 1 < NIT) {
            int s = (it + 1) >> 3, kc = (it + 1) & 7;
            uint32_t stg = (uint32_t)(((it + 1) & 1) * STAGE_B);
#pragma unroll
            for (int j2 = 0; j2 < 2; j2++) {
                int seg = s0 + 2 * j2;
                uint32_t d = drow + stg + (uint32_t)(seg * 16);
                size_t go = (size_t)(kc * 32 + seg * 8);
                cpa16(d,          pA[s] + arow + go, av);
                cpa16(d + TILE_B, pB[s] + brow + go, 1);
            }
            CP_COMMIT();
            CP_WAIT1();
        } else {
            CP_WAIT0();
        }
        __syncthreads();

        uint32_t base = sb + (uint32_t)((it & 1) * STAGE_B);
#pragma unroll
        for (int kk = 0; kk < 32; kk += 16) {
            uint32_t koff = (uint32_t)(kk * 2);
            uint32_t b[4][2];
#pragma unroll
            for (int nb = 0; nb < 2; nb++) {
                uint32_t off = offB + koff + (uint32_t)(nb * 16 * TROWB);
                uint32_t t0, t1, t2, t3;
                ldm4(base + TILE_B + off, t0, t1, t2, t3);
                b[nb * 2][0] = t0; b[nb * 2][1] = t1;
                b[nb * 2 + 1][0] = t2; b[nb * 2 + 1][1] = t3;
            }
            uint32_t a[4];
#pragma unroll
            for (int mi = 0; mi < 4; mi++) {
                uint32_t off = offA + koff + (uint32_t)(mi * 16 * TROWB);
                ldm4(base + off, a[0], a[1], a[2], a[3]);
#pragma unroll
                for (int nj = 0; nj < 4; nj++)
                    mma16816(acc[mi * 4 + nj], a, b[nj]);
            }
        }
        __syncthreads();   // protect the stage being prefetched next iteration
    }

    // epilogue
    unsigned short* oH = (outp >= 0) ? bufp(outp) : nullptr;
#pragma unroll
    for (int mi = 0; mi < 4; mi++) {
#pragma unroll
        for (int nj = 0; nj < 4; nj++) {
            float* c = acc[mi * 4 + nj];
            int col = bn + wn * 32 + nj * 8 + (lane & 3) * 2;
            float bi0 = bias[col], bi1 = bias[col + 1];
#pragma unroll
            for (int half = 0; half < 2; half++) {
                int r = bm + wm * 64 + mi * 16 + (lane >> 2) + half * 8;
                if (r >= NN) continue;
                float v0 = c[half * 2] + bi0;
                float v1 = c[half * 2 + 1] + bi1;
                if (relu) { v0 = fmaxf(v0, 0.f); v1 = fmaxf(v1, 0.f); }
                if (oH) {
                    *(ushort2*)(oH + (size_t)r * D + col) = make_ushort2(
                        __half_as_ushort(__float2half_rn(v0)),
                        __half_as_ushort(__float2half_rn(v1)));
                } else {
                    *(float2*)(cext + (size_t)r * ldc + col) = make_float2(v0, v1);
                }
            }
        }
    }
}

// ---------------- row-wise log_softmax over 128 cols, in place ----------------
__global__ void k_lsm(float* __restrict__ out) {
    int r = blockIdx.x;
    int t = threadIdx.x;
    float v = out[(size_t)r * DOUT + t];
    __shared__ float smax[4], ssum[4];
    float m = v;
#pragma unroll
    for (int o = 16; o; o >>= 1) m = fmaxf(m, __shfl_xor_sync(0xffffffffu, m, o));
    if ((t & 31) == 0) smax[t >> 5] = m;
    __syncthreads();
    float mm = fmaxf(fmaxf(smax[0], smax[1]), fmaxf(smax[2], smax[3]));
    float e = expf(v - mm);
    float sum = e;
#pragma unroll
    for (int o = 16; o; o >>= 1) sum += __shfl_xor_sync(0xffffffffu, sum, o);
    if ((t & 31) == 0) ssum[t >> 5] = sum;
    __syncthreads();
    float tot = ssum[0] + ssum[1] + ssum[2] + ssum[3];
    out[(size_t)r * DOUT + t] = v - mm - logf(tot);
}

// ---------------- launch: kernel launches ONLY ----------------
extern "C" void kernel_launch(void* const* d_in, const int* in_sizes, int n_in,
                              void* d_out, int out_size) {
    const float* x  = (const float*)d_in[0];
    const void*  ei = d_in[1];
    const float* wl = (const float*)d_in[2];
    const float* bl = (const float*)d_in[3];
    const float* wr = (const float*)d_in[4];
    const float* w1 = (const float*)d_in[5];
    const float* b1 = (const float*)d_in[6];
    const float* w2 = (const float*)d_in[7];
    const float* b2 = (const float*)d_in[8];
    float* out = (float*)d_out;

    cudaFuncSetAttribute(k_mma, cudaFuncAttributeMaxDynamicSharedMemorySize, SMEM_DYN);

    // operand prep
    k_split_x<<<(NN * D / 4 + 255) / 256, 256>>>(x);
    k_split_wall<<<(7 * 65536 + D * DOUT + 255) / 256, 256>>>(wl, wr, w1, w2);

    // CSR by dst
    k_detect<<<1, 512>>>((const int*)ei);
    k_zero_deg<<<(NN + 255) / 256, 256>>>();
    k_hist<<<(NE + 255) / 256, 256>>>(ei);
    k_scan1<<<SCAN_B, 1024>>>();
    k_scan2<<<1, 1>>>();
    k_scan3<<<(NN + 255) / 256, 256>>>();
    k_fill<<<(NE + 255) / 256, 256>>>(ei);

    dim3 g2((NN + 127) / 128, 2);
    dim3 g1((NN + 127) / 128, 1);

    // layer 0: agg(x); h0 = relu(agg@wl0 + x@wr0 + bl0)
    k_agg<<<4096, 256>>>(0);
    k_mma<<<g2, 256, SMEM_DYN>>>(3, 0, 1, 1, nullptr, 0 * 65536, 3 * 65536, bl + 0 * D, 1, D);
    // layer 1: agg(h0); h1 = relu(...)
    k_agg<<<4096, 256>>>(1);
    k_mma<<<g2, 256, SMEM_DYN>>>(3, 1, 1, 2, nullptr, 1 * 65536, 4 * 65536, bl + 1 * D, 1, D);
    // layer 2: agg(h1); h0 = relu(...)
    k_agg<<<4096, 256>>>(2);
    k_mma<<<g2, 256, SMEM_DYN>>>(3, 2, 1, 1, nullptr, 2 * 65536, 5 * 65536, bl + 2 * D, 1, D);
    // post_mp: z = h0@w1 + b1 ; out = z@w2 + b2
    k_mma<<<g2, 256, SMEM_DYN>>>(1, 1, 0, 3, nullptr, 6 * 65536, 0, b1, 0, D);
    k_mma<<<g1, 256, SMEM_DYN>>>(3, 3, 0, -1, out, 7 * 65536, 0, b2, 0, DOUT);
    k_lsm<<<NN, 128>>>(out);
}

// round 11
// speedup vs baseline: 2.0450x; 1.1971x over previous
#include <cuda_runtime.h>
#include <cuda_fp16.h>
#include <cstdint>

#define NN 50000
#define NE 800000
#define D 256
#define DOUT 128
#define SCAN_B 49   // ceil(50000/1024)

// ---------------- device scratch (static: no allocation allowed) ----------------
__device__ unsigned short g_x16[NN * D];     // fp16 activations
__device__ unsigned short g_h0[NN * D];
__device__ unsigned short g_h1[NN * D];
__device__ unsigned short g_agg[NN * D];     // agg / z buffer
__device__ unsigned short g_wt[8 * 65536];   // transposed fp16 weights
__device__ float g_deginv[NN];
__device__ int   g_deg[NN];
__device__ int   g_rowptr[NN + 1];
__device__ int   g_cursor[NN];
__device__ int   g_col[NE];
__device__ int   g_bsum[SCAN_B];
__device__ int   g_is64;

// ids: 0 -> x, 1 -> h0, 2 -> h1, 3 -> agg/z
__device__ __forceinline__ unsigned short* bufp(int id) {
    if (id == 0) return g_x16;
    if (id == 1) return g_h0;
    if (id == 2) return g_h1;
    return g_agg;
}

__device__ __forceinline__ int edge_at(const void* ei, int word) {
    if (g_is64) return (int)((const long long*)ei)[word];
    return ((const int*)ei)[word];
}

__device__ __forceinline__ uint32_t smem_u32(const void* p) {
    uint32_t a;
    asm("{ .reg .u64 t; cvta.to.shared.u64 t, %1; cvt.u32.u64 %0, t; }" : "=r"(a) : "l"(p));
    return a;
}
__device__ __forceinline__ void ldm4(uint32_t addr, uint32_t& r0, uint32_t& r1,
                                     uint32_t& r2, uint32_t& r3) {
    asm volatile("ldmatrix.sync.aligned.m8n8.x4.shared.b16 {%0,%1,%2,%3}, [%4];"
                 : "=r"(r0), "=r"(r1), "=r"(r2), "=r"(r3) : "r"(addr));
}
__device__ __forceinline__ void mma16816(float* c, const uint32_t* a, const uint32_t* b) {
    asm volatile("mma.sync.aligned.m16n8k16.row.col.f32.f16.f16.f32 "
                 "{%0,%1,%2,%3}, {%4,%5,%6,%7}, {%8,%9}, {%0,%1,%2,%3};"
                 : "+f"(c[0]), "+f"(c[1]), "+f"(c[2]), "+f"(c[3])
                 : "r"(a[0]), "r"(a[1]), "r"(a[2]), "r"(a[3]), "r"(b[0]), "r"(b[1]));
}
__device__ __forceinline__ void cpa16(uint32_t dst, const void* src, int valid) {
    asm volatile("cp.async.cg.shared.global [%0], [%1], 16, %2;"
                 :: "r"(dst), "l"(src), "r"(valid ? 16 : 0));
}
#define CP_COMMIT() asm volatile("cp.async.commit_group;" ::: "memory")
#define CP_WAIT1()  asm volatile("cp.async.wait_group 1;" ::: "memory")
#define CP_WAIT0()  asm volatile("cp.async.wait_group 0;" ::: "memory")

// ---------------- prep: x -> fp16 AND all weights transposed fp16, one kernel ----------------
#define NPREPX (NN * D / 4)           // 3.2M (x, 4 elems/thread)
__global__ void k_prep(const float* __restrict__ x,
                       const float* __restrict__ wl, const float* __restrict__ wr,
                       const float* __restrict__ w1, const float* __restrict__ w2) {
    int idx = blockIdx.x * blockDim.x + threadIdx.x;
    if (idx < NPREPX) {
        int i = idx * 4;
#pragma unroll
        for (int j = 0; j < 4; j++)
            g_x16[i + j] = __half_as_ushort(__float2half_rn(x[i + j]));
    } else if (idx < NPREPX + 7 * 65536) {
        int q = idx - NPREPX;
        int m = q >> 16, t = q & 65535;
        const float* src = (m < 3) ? (wl + (size_t)m * 65536)
                         : (m < 6) ? (wr + (size_t)(m - 3) * 65536) : w1;
        int k = t >> 8, n = t & 255;
        g_wt[m * 65536 + n * 256 + k] = __half_as_ushort(__float2half_rn(src[t]));
    } else if (idx < NPREPX + 7 * 65536 + D * DOUT) {
        int t = idx - NPREPX - 7 * 65536;
        int k = t >> 7, n = t & 127;
        g_wt[7 * 65536 + n * 256 + k] = __half_as_ushort(__float2half_rn(w2[t]));
    }
}

// ---------------- zero degrees + dtype probe (block 0) ----------------
__global__ void k_zero(const int* __restrict__ ei32) {
    int i = blockIdx.x * blockDim.x + threadIdx.x;
    if (i < NN) g_deg[i] = 0;
    if (blockIdx.x == 0) {
        __shared__ int nz;
        if (threadIdx.x == 0) nz = 0;
        __syncthreads();
        if (ei32[2 * threadIdx.x + 1] != 0) atomicOr(&nz, 1);
        __syncthreads();
        if (threadIdx.x == 0) g_is64 = nz ? 0 : 1;
    }
}

// ---------------- CSR build ----------------
__global__ void k_hist(const void* __restrict__ ei) {
    int e = blockIdx.x * blockDim.x + threadIdx.x;
    if (e < NE) {
        unsigned d = (unsigned)edge_at(ei, NE + e);
        if (d < NN) atomicAdd(&g_deg[d], 1);
    }
}
__global__ void k_scan1() {
    __shared__ int s[1024];
    int t = threadIdx.x;
    int i = blockIdx.x * 1024 + t;
    int v = (i < NN) ? g_deg[i] : 0;
    s[t] = v;
    __syncthreads();
    for (int o = 1; o < 1024; o <<= 1) {
        int a = (t >= o) ? s[t - o] : 0;
        __syncthreads();
        s[t] += a;
        __syncthreads();
    }
    if (i < NN) g_rowptr[i] = s[t] - v;
    if (t == 1023) g_bsum[blockIdx.x] = s[1023];
}
__global__ void k_scan2() {
    int run = 0;
    for (int b = 0; b < SCAN_B; b++) { int t = g_bsum[b]; g_bsum[b] = run; run += t; }
}
__global__ void k_scan3() {
    int i = blockIdx.x * blockDim.x + threadIdx.x;
    if (i < NN) {
        int rp = g_rowptr[i] + g_bsum[i >> 10];
        g_rowptr[i] = rp;
        g_cursor[i] = rp;
        int dg = g_deg[i];
        g_deginv[i] = 1.0f / (float)(dg > 0 ? dg : 1);
    }
    if (i == 0) g_rowptr[NN] = NE;
}
__global__ void k_fill(const void* __restrict__ ei) {
    int e = blockIdx.x * blockDim.x + threadIdx.x;
    if (e < NE) {
        unsigned d = (unsigned)edge_at(ei, NE + e);
        unsigned s = (unsigned)edge_at(ei, e);
        if (d < NN && s < NN) {
            int pos = atomicAdd(&g_cursor[d], 1);
            g_col[pos] = (int)s;
        }
    }
}

// ---------------- mean aggregation (fp16, vectorized: 128 thr x half2) ----------------
__global__ void k_agg(int src_id) {
    const unsigned int* __restrict__ H = (const unsigned int*)bufp(src_id);  // 128 uints/row
    unsigned int* __restrict__ O = (unsigned int*)g_agg;
    __shared__ int sc[128];
    int t = threadIdx.x;   // 0..127
    for (int r = blockIdx.x; r < NN; r += gridDim.x) {
        int beg = g_rowptr[r], end = g_rowptr[r + 1];
        float a0 = 0.f, a1 = 0.f;
        for (int base = beg; base < end; base += 128) {
            int cnt = min(128, end - base);
            __syncthreads();
            if (t < cnt) sc[t] = g_col[base + t];
            __syncthreads();
            int i = 0;
            for (; i + 4 <= cnt; i += 4) {
                unsigned int v0 = H[(size_t)sc[i]     * 128 + t];
                unsigned int v1 = H[(size_t)sc[i + 1] * 128 + t];
                unsigned int v2 = H[(size_t)sc[i + 2] * 128 + t];
                unsigned int v3 = H[(size_t)sc[i + 3] * 128 + t];
                float2 f0 = __half22float2(*reinterpret_cast<__half2*>(&v0));
                float2 f1 = __half22float2(*reinterpret_cast<__half2*>(&v1));
                float2 f2 = __half22float2(*reinterpret_cast<__half2*>(&v2));
                float2 f3 = __half22float2(*reinterpret_cast<__half2*>(&v3));
                a0 += (f0.x + f1.x) + (f2.x + f3.x);
                a1 += (f0.y + f1.y) + (f2.y + f3.y);
            }
            for (; i < cnt; i++) {
                unsigned int v = H[(size_t)sc[i] * 128 + t];
                float2 f = __half22float2(*reinterpret_cast<__half2*>(&v));
                a0 += f.x;
                a1 += f.y;
            }
        }
        float di = g_deginv[r];
        __half2 o = __floats2half2_rn(a0 * di, a1 * di);
        O[(size_t)r * 128 + t] = *reinterpret_cast<unsigned int*>(&o);
    }
}

// ---------------- fp16 tensor-core GEMM, 2-stage cp.async, K-chunk 32 ----------------
// C[128x128 tile] = sum_src A@B^T, fused bias(+relu).
// Tiles A/B: 128 rows x 32 fp16, 80 B padded rows (conflict-free ldmatrix).
#define TROWB   80
#define TILE_B  (128 * TROWB)       // 10240
#define STAGE_B (2 * TILE_B)        // 20480
#define SMEM_DYN (2 * STAGE_B)      // 40960 (40 KB)

__global__ __launch_bounds__(256, 2)
void k_mma(int a1id, int a2id, int dual, int outp,
           float* __restrict__ cext, int woff1, int woff2,
           const float* __restrict__ bias, int relu, int ldc) {
    extern __shared__ __align__(16) unsigned char sT[];
    uint32_t sb = smem_u32(sT);
    int tid = threadIdx.x;
    int lane = tid & 31;
    int wid = tid >> 5;
    int wm = wid & 1;        // 2 warp-rows (64 rows)
    int wn = wid >> 1;       // 4 warp-cols (32 cols)
    int bm = blockIdx.x * 128;
    int bn = blockIdx.y * 128;

    const unsigned short* pA[2] = { bufp(a1id), bufp(a2id) };
    const unsigned short* pB[2] = { g_wt + woff1, g_wt + woff2 };

    float acc[16][4];
#pragma unroll
    for (int i = 0; i < 16; i++)
#pragma unroll
        for (int j = 0; j < 4; j++) acc[i][j] = 0.f;

    // loader: 128 rows x 32 fp16 (64 B) per tile; thread -> (row, 16B segment pair)
    int lrow = tid >> 1, s0 = tid & 1;
    int gr = bm + lrow;
    int av = gr < NN;
    size_t arow = (size_t)(av ? gr : 0) * D;
    size_t brow = (size_t)(bn + lrow) * D;
    uint32_t drow = sb + (uint32_t)(lrow * TROWB);

    // ldmatrix lane-address components (proven mapping, stride 80)
    int grp = lane >> 3, lr = lane & 7;
    int a_r = wm * 64 + ((grp & 1) << 3) + lr;
    int a_c = (grp & 2) ? 8 : 0;
    int b_r = wn * 32 + ((grp & 2) << 2) + lr;
    int b_c = (grp & 1) << 3;
    uint32_t offA = (uint32_t)(a_r * TROWB + a_c * 2);
    uint32_t offB = (uint32_t)(b_r * TROWB + b_c * 2);

    int NIT = dual ? 16 : 8;

    // prologue: iteration 0 -> stage 0
#pragma unroll
    for (int j2 = 0; j2 < 2; j2++) {
        int seg = s0 + 2 * j2;
        uint32_t d = drow + (uint32_t)(seg * 16);
        size_t go = (size_t)(seg * 8);
        cpa16(d,          pA[0] + arow + go, av);
        cpa16(d + TILE_B, pB[0] + brow + go, 1);
    }
    CP_COMMIT();

    for (int it = 0; it < NIT; it++) {
        if (it + 1 < NIT) {
            int s = (it + 1) >> 3, kc = (it + 1) & 7;
            uint32_t stg = (uint32_t)(((it + 1) & 1) * STAGE_B);
#pragma unroll
            for (int j2 = 0; j2 < 2; j2++) {
                int seg = s0 + 2 * j2;
                uint32_t d = drow + stg + (uint32_t)(seg * 16);
                size_t go = (size_t)(kc * 32 + seg * 8);
                cpa16(d,          pA[s] + arow + go, av);
                cpa16(d + TILE_B, pB[s] + brow + go, 1);
            }
            CP_COMMIT();
            CP_WAIT1();
        } else {
            CP_WAIT0();
        }
        __syncthreads();

        uint32_t base = sb + (uint32_t)((it & 1) * STAGE_B);
#pragma unroll
        for (int kk = 0; kk < 32; kk += 16) {
            uint32_t koff = (uint32_t)(kk * 2);
            uint32_t b[4][2];
#pragma unroll
            for (int nb = 0; nb < 2; nb++) {
                uint32_t off = offB + koff + (uint32_t)(nb * 16 * TROWB);
                uint32_t t0, t1, t2, t3;
                ldm4(base + TILE_B + off, t0, t1, t2, t3);
                b[nb * 2][0] = t0; b[nb * 2][1] = t1;
                b[nb * 2 + 1][0] = t2; b[nb * 2 + 1][1] = t3;
            }
            uint32_t a[4];
#pragma unroll
            for (int mi = 0; mi < 4; mi++) {
                uint32_t off = offA + koff + (uint32_t)(mi * 16 * TROWB);
                ldm4(base + off, a[0], a[1], a[2], a[3]);
#pragma unroll
                for (int nj = 0; nj < 4; nj++)
                    mma16816(acc[mi * 4 + nj], a, b[nj]);
            }
        }
        __syncthreads();   // protect the stage being prefetched next iteration
    }

    // epilogue
    unsigned short* oH = (outp >= 0) ? bufp(outp) : nullptr;
#pragma unroll
    for (int mi = 0; mi < 4; mi++) {
#pragma unroll
        for (int nj = 0; nj < 4; nj++) {
            float* c = acc[mi * 4 + nj];
            int col = bn + wn * 32 + nj * 8 + (lane & 3) * 2;
            float bi0 = bias[col], bi1 = bias[col + 1];
#pragma unroll
            for (int half = 0; half < 2; half++) {
                int r = bm + wm * 64 + mi * 16 + (lane >> 2) + half * 8;
                if (r >= NN) continue;
                float v0 = c[half * 2] + bi0;
                float v1 = c[half * 2 + 1] + bi1;
                if (relu) { v0 = fmaxf(v0, 0.f); v1 = fmaxf(v1, 0.f); }
                if (oH) {
                    *(ushort2*)(oH + (size_t)r * D + col) = make_ushort2(
                        __half_as_ushort(__float2half_rn(v0)),
                        __half_as_ushort(__float2half_rn(v1)));
                } else {
                    *(float2*)(cext + (size_t)r * ldc + col) = make_float2(v0, v1);
                }
            }
        }
    }
}

// ---------------- row-wise log_softmax over 128 cols, 2 rows/block ----------------
__global__ void k_lsm(float* __restrict__ out) {
    int r = blockIdx.x * 2 + (threadIdx.x >> 7);
    int t = threadIdx.x & 127;
    if (r >= NN) return;
    float v = out[(size_t)r * DOUT + t];
    __shared__ float smax[2][4], ssum[2][4];
    int g = threadIdx.x >> 7;
    float m = v;
#pragma unroll
    for (int o = 16; o; o >>= 1) m = fmaxf(m, __shfl_xor_sync(0xffffffffu, m, o));
    if ((t & 31) == 0) smax[g][t >> 5] = m;
    __syncthreads();
    float mm = fmaxf(fmaxf(smax[g][0], smax[g][1]), fmaxf(smax[g][2], smax[g][3]));
    float e = expf(v - mm);
    float sum = e;
#pragma unroll
    for (int o = 16; o; o >>= 1) sum += __shfl_xor_sync(0xffffffffu, sum, o);
    if ((t & 31) == 0) ssum[g][t >> 5] = sum;
    __syncthreads();
    float tot = ssum[g][0] + ssum[g][1] + ssum[g][2] + ssum[g][3];
    out[(size_t)r * DOUT + t] = v - mm - logf(tot);
}

// ---------------- launch: kernel launches ONLY ----------------
extern "C" void kernel_launch(void* const* d_in, const int* in_sizes, int n_in,
                              void* d_out, int out_size) {
    const float* x  = (const float*)d_in[0];
    const void*  ei = d_in[1];
    const float* wl = (const float*)d_in[2];
    const float* bl = (const float*)d_in[3];
    const float* wr = (const float*)d_in[4];
    const float* w1 = (const float*)d_in[5];
    const float* b1 = (const float*)d_in[6];
    const float* w2 = (const float*)d_in[7];
    const float* b2 = (const float*)d_in[8];
    float* out = (float*)d_out;

    cudaFuncSetAttribute(k_mma, cudaFuncAttributeMaxDynamicSharedMemorySize, SMEM_DYN);

    // operand prep + CSR by dst
    k_prep<<<(NPREPX + 7 * 65536 + D * DOUT + 255) / 256, 256>>>(x, wl, wr, w1, w2);
    k_zero<<<(NN + 255) / 256, 256>>>((const int*)ei);
    k_hist<<<(NE + 255) / 256, 256>>>(ei);
    k_scan1<<<SCAN_B, 1024>>>();
    k_scan2<<<1, 1>>>();
    k_scan3<<<(NN + 255) / 256, 256>>>();
    k_fill<<<(NE + 255) / 256, 256>>>(ei);

    dim3 g2((NN + 127) / 128, 2);
    dim3 g1((NN + 127) / 128, 1);

    // layer 0: agg(x); h0 = relu(agg@wl0 + x@wr0 + bl0)
    k_agg<<<6144, 128>>>(0);
    k_mma<<<g2, 256, SMEM_DYN>>>(3, 0, 1, 1, nullptr, 0 * 65536, 3 * 65536, bl + 0 * D, 1, D);
    // layer 1: agg(h0); h1 = relu(...)
    k_agg<<<6144, 128>>>(1);
    k_mma<<<g2, 256, SMEM_DYN>>>(3, 1, 1, 2, nullptr, 1 * 65536, 4 * 65536, bl + 1 * D, 1, D);
    // layer 2: agg(h1); h0 = relu(...)
    k_agg<<<6144, 128>>>(2);
    k_mma<<<g2, 256, SMEM_DYN>>>(3, 2, 1, 1, nullptr, 2 * 65536, 5 * 65536, bl + 2 * D, 1, D);
    // post_mp: z = h0@w1 + b1 ; out = z@w2 + b2
    k_mma<<<g2, 256, SMEM_DYN>>>(1, 1, 0, 3, nullptr, 6 * 65536, 0, b1, 0, D);
    k_mma<<<g1, 256, SMEM_DYN>>>(3, 3, 0, -1, out, 7 * 65536, 0, b2, 0, DOUT);
    k_lsm<<<(NN + 1) / 2, 256>>>(out);
}